// round 2
// baseline (speedup 1.0000x reference)
#include <cuda_runtime.h>
#include <math.h>

#define N_NODES   50000
#define NODE_DIM  128
#define IN_DIM    384
#define OUT_DIM   256
#define TILE_E    64
#define EPS       1e-5f

// Scratch for normalized node features (25.6 MB). Static device array — no allocs.
__device__ float g_xn[(size_t)N_NODES * NODE_DIM];

// ---------------------------------------------------------------------------
// Kernel 1: per-node LayerNorm. One warp per row, float4 loads.
// ---------------------------------------------------------------------------
__global__ __launch_bounds__(256) void node_ln_kernel(const float* __restrict__ x,
                                                      const float* __restrict__ gamma,
                                                      const float* __restrict__ beta) {
    int row = blockIdx.x * 8 + (threadIdx.x >> 5);
    if (row >= N_NODES) return;
    int lane = threadIdx.x & 31;

    float4 v = ((const float4*)(x + (size_t)row * NODE_DIM))[lane];
    float s  = v.x + v.y + v.z + v.w;
    float ss = v.x * v.x + v.y * v.y + v.z * v.z + v.w * v.w;
    #pragma unroll
    for (int o = 16; o; o >>= 1) {
        s  += __shfl_xor_sync(0xffffffffu, s,  o);
        ss += __shfl_xor_sync(0xffffffffu, ss, o);
    }
    float mu  = s * (1.0f / 128.0f);
    float var = ss * (1.0f / 128.0f) - mu * mu;
    float inv = rsqrtf(var + EPS);

    float4 g = ((const float4*)gamma)[lane];
    float4 b = ((const float4*)beta)[lane];
    float4 o4;
    o4.x = (v.x - mu) * inv * g.x + b.x;
    o4.y = (v.y - mu) * inv * g.y + b.y;
    o4.z = (v.z - mu) * inv * g.z + b.z;
    o4.w = (v.w - mu) * inv * g.w + b.w;
    ((float4*)(g_xn + (size_t)row * NODE_DIM))[lane] = o4;
}

// ---------------------------------------------------------------------------
// Kernel 2: edge GEMM (64 edges x 256 outs, K=384) + fused gated residual + LN.
// SMEM: A[384][64] gathered once, B chunk [16][256] (reg-prefetched), raw[64][256].
// ---------------------------------------------------------------------------
__global__ __launch_bounds__(256) void edge_kernel(const int*   __restrict__ ei,
                                                   const float* __restrict__ ea,
                                                   const float* __restrict__ W,
                                                   const float* __restrict__ bias,
                                                   const float* __restrict__ eg,
                                                   const float* __restrict__ eb,
                                                   float* __restrict__ out,
                                                   int E) {
    extern __shared__ float smem[];
    float* A_s    = smem;                        // IN_DIM * TILE_E  (transposed: [k][e])
    float* B_s    = A_s + IN_DIM * TILE_E;       // 16 * OUT_DIM
    float* raw_s  = B_s + 16 * OUT_DIM;          // TILE_E * OUT_DIM
    float* bias_s = raw_s + TILE_E * OUT_DIM;    // OUT_DIM

    int tid = threadIdx.x;
    int e0  = blockIdx.x * TILE_E;
    int ne  = min(TILE_E, E - e0);

    if (tid < OUT_DIM / 4)
        ((float4*)bias_s)[tid] = ((const float4*)bias)[tid];

    // --- Gather A tile: 4 threads per edge, each loads 96 of 384 columns ---
    {
        int le = tid >> 2;          // 0..63
        int q  = tid & 3;           // 0..3
        if (le < ne) {
            int e  = e0 + le;
            int sN = ei[e];
            int dN = ei[E + e];
            const float* rs = g_xn + (size_t)sN * NODE_DIM;
            const float* rd = g_xn + (size_t)dN * NODE_DIM;
            const float* re = ea + (size_t)e * NODE_DIM;
            #pragma unroll
            for (int c4 = 0; c4 < 24; c4++) {
                int c = q * 96 + c4 * 4;
                float4 v;
                if (c < 128)       v = *(const float4*)(rs + c);
                else if (c < 256)  v = *(const float4*)(rd + (c - 128));
                else               v = *(const float4*)(re + (c - 256));
                A_s[(c + 0) * TILE_E + le] = v.x;
                A_s[(c + 1) * TILE_E + le] = v.y;
                A_s[(c + 2) * TILE_E + le] = v.z;
                A_s[(c + 3) * TILE_E + le] = v.w;
            }
        } else {
            #pragma unroll
            for (int c4 = 0; c4 < 24; c4++) {
                int c = q * 96 + c4 * 4;
                A_s[(c + 0) * TILE_E + le] = 0.f;
                A_s[(c + 1) * TILE_E + le] = 0.f;
                A_s[(c + 2) * TILE_E + le] = 0.f;
                A_s[(c + 3) * TILE_E + le] = 0.f;
            }
        }
    }

    // --- GEMM mainloop: K in 24 chunks of 16, B chunk prefetched into regs ---
    const float4* Wv = (const float4*)W;   // W row-major [384][256] -> chunk c at float4 idx c*1024
    float4 breg[4];
    #pragma unroll
    for (int i = 0; i < 4; i++) breg[i] = Wv[tid + i * 256];
    #pragma unroll
    for (int i = 0; i < 4; i++) ((float4*)B_s)[tid + i * 256] = breg[i];
    __syncthreads();   // A_s, B_s(chunk0), bias_s ready

    float acc[8][8];
    #pragma unroll
    for (int i = 0; i < 8; i++)
        #pragma unroll
        for (int j = 0; j < 8; j++) acc[i][j] = 0.f;

    int tx = tid & 31;      // 32 column-groups of 8 -> cols tx*8..tx*8+7
    int ty = tid >> 5;      // 8 row-groups of 8    -> rows ty*8..ty*8+7

    for (int c = 0; c < 24; c++) {
        if (c < 23) {
            #pragma unroll
            for (int i = 0; i < 4; i++) breg[i] = Wv[(c + 1) * 1024 + tid + i * 256];
        }
        #pragma unroll
        for (int kk = 0; kk < 16; kk++) {
            int k = c * 16 + kk;
            float4 a0 = *(const float4*)&A_s[k * TILE_E + ty * 8];
            float4 a1 = *(const float4*)&A_s[k * TILE_E + ty * 8 + 4];
            float4 b0 = *(const float4*)&B_s[kk * OUT_DIM + tx * 8];
            float4 b1 = *(const float4*)&B_s[kk * OUT_DIM + tx * 8 + 4];
            float a[8]  = {a0.x, a0.y, a0.z, a0.w, a1.x, a1.y, a1.z, a1.w};
            float bv[8] = {b0.x, b0.y, b0.z, b0.w, b1.x, b1.y, b1.z, b1.w};
            #pragma unroll
            for (int i = 0; i < 8; i++)
                #pragma unroll
                for (int j = 0; j < 8; j++)
                    acc[i][j] = fmaf(a[i], bv[j], acc[i][j]);
        }
        __syncthreads();
        if (c < 23) {
            #pragma unroll
            for (int i = 0; i < 4; i++) ((float4*)B_s)[tid + i * 256] = breg[i];
            __syncthreads();
        }
    }

    // --- Epilogue part 1: bias + relu -> raw_s ---
    float blo[8];
    #pragma unroll
    for (int j = 0; j < 8; j++) blo[j] = bias_s[tx * 8 + j];
    #pragma unroll
    for (int i = 0; i < 8; i++) {
        float4 r0, r1;
        r0.x = fmaxf(acc[i][0] + blo[0], 0.f);
        r0.y = fmaxf(acc[i][1] + blo[1], 0.f);
        r0.z = fmaxf(acc[i][2] + blo[2], 0.f);
        r0.w = fmaxf(acc[i][3] + blo[3], 0.f);
        r1.x = fmaxf(acc[i][4] + blo[4], 0.f);
        r1.y = fmaxf(acc[i][5] + blo[5], 0.f);
        r1.z = fmaxf(acc[i][6] + blo[6], 0.f);
        r1.w = fmaxf(acc[i][7] + blo[7], 0.f);
        *(float4*)&raw_s[(ty * 8 + i) * OUT_DIM + tx * 8]     = r0;
        *(float4*)&raw_s[(ty * 8 + i) * OUT_DIM + tx * 8 + 4] = r1;
    }
    __syncthreads();

    // --- Epilogue part 2: gated residual + per-edge LayerNorm (warp per edge) ---
    int lane = tx;
    int w    = ty;
    float egv[4], ebv[4];
    #pragma unroll
    for (int i = 0; i < 4; i++) { egv[i] = eg[lane + 32 * i]; ebv[i] = eb[lane + 32 * i]; }

    for (int it = 0; it < 8; it++) {
        int le = it * 8 + w;
        if (le >= ne) continue;   // uniform per warp
        float o[4], s = 0.f, ss = 0.f;
        #pragma unroll
        for (int i = 0; i < 4; i++) {
            int dd = lane + 32 * i;
            float dl  = raw_s[le * OUT_DIM + dd];
            float gt  = raw_s[le * OUT_DIM + 128 + dd];
            float eav = A_s[(256 + dd) * TILE_E + le];   // edge_attr still resident
            float sg  = 1.0f / (1.0f + expf(-gt));
            float ov  = eav + sg * dl;
            o[i] = ov; s += ov; ss += ov * ov;
        }
        #pragma unroll
        for (int off = 16; off; off >>= 1) {
            s  += __shfl_xor_sync(0xffffffffu, s,  off);
            ss += __shfl_xor_sync(0xffffffffu, ss, off);
        }
        float mu  = s * (1.0f / 128.0f);
        float inv = rsqrtf(ss * (1.0f / 128.0f) - mu * mu + EPS);
        #pragma unroll
        for (int i = 0; i < 4; i++) {
            int dd = lane + 32 * i;
            out[(size_t)(e0 + le) * 128 + dd] = (o[i] - mu) * inv * egv[i] + ebv[i];
        }
    }
}

// ---------------------------------------------------------------------------
extern "C" void kernel_launch(void* const* d_in, const int* in_sizes, int n_in,
                              void* d_out, int out_size) {
    const float* x  = (const float*)d_in[0];
    const int*   ei = (const int*)  d_in[1];
    const float* ea = (const float*)d_in[2];
    const float* W  = (const float*)d_in[3];
    const float* b  = (const float*)d_in[4];
    const float* ng = (const float*)d_in[5];
    const float* nb = (const float*)d_in[6];
    const float* eg = (const float*)d_in[7];
    const float* eb = (const float*)d_in[8];
    float* out = (float*)d_out;

    int E = in_sizes[2] / NODE_DIM;   // 500000

    node_ln_kernel<<<(N_NODES + 7) / 8, 256>>>(x, ng, nb);

    const int smem_bytes = (IN_DIM * TILE_E + 16 * OUT_DIM + TILE_E * OUT_DIM + OUT_DIM) * (int)sizeof(float);
    cudaFuncSetAttribute(edge_kernel, cudaFuncAttributeMaxDynamicSharedMemorySize, smem_bytes);
    edge_kernel<<<(E + TILE_E - 1) / TILE_E, 256, smem_bytes>>>(ei, ea, W, b, eg, eb, out, E);
}

// round 4
// speedup vs baseline: 2.7576x; 2.7576x over previous
#include <cuda_runtime.h>
#include <math.h>
#include <stdint.h>

#define N_NODES   50000
#define NODE_DIM  128
#define IN_DIM    384
#define OUT_DIM   256
#define EPS       1e-5f
#define TILE_M    128
#define KC        32
#define NCH       12

// ---- static device scratch (no allocs) ----
__device__ float g_xn[(size_t)N_NODES * NODE_DIM];   // node-LN output, pre-rounded to tf32
__device__ float g_wc[(size_t)IN_DIM * OUT_DIM];     // W pre-rounded to tf32

// ---- smem layout (float offsets) ----
#define A_STRIDE 36
#define B_STRIDE 264
#define R_STRIDE 257
#define SM_A0    0
#define SM_A1    (SM_A0 + TILE_M * A_STRIDE)            // 4608
#define SM_B0    (SM_A1 + TILE_M * A_STRIDE)            // 9216
#define SM_B1    (SM_B0 + KC * B_STRIDE)                // 17664
#define SM_RAW   0                                      // aliases A/B after mainloop
#define SM_MISC  (TILE_M * R_STRIDE)                    // 32896
#define SM_BIAS  (SM_MISC)
#define SM_SN    (SM_MISC + 256)
#define SM_DN    (SM_MISC + 384)
#define SM_MU    (SM_MISC + 512)
#define SM_INV   (SM_MISC + 640)
#define SMEM_FLOATS (SM_MISC + 768)
#define SMEM_BYTES  (SMEM_FLOATS * 4)                   // 134656 B

static __device__ __forceinline__ float tf32r(float x) {
    uint32_t t;
    asm("cvt.rna.tf32.f32 %0, %1;" : "=r"(t) : "f"(x));
    return __uint_as_float(t);
}
static __device__ __forceinline__ void cp16(uint32_t dst, const void* src) {
    asm volatile("cp.async.cg.shared.global [%0], [%1], 16;" :: "r"(dst), "l"(src));
}
static __device__ __forceinline__ void mma_tf32(float* c, const uint32_t* a, const uint32_t* b) {
    asm volatile(
        "mma.sync.aligned.m16n8k8.row.col.f32.tf32.tf32.f32 "
        "{%0,%1,%2,%3}, {%4,%5,%6,%7}, {%8,%9}, {%0,%1,%2,%3};"
        : "+f"(c[0]), "+f"(c[1]), "+f"(c[2]), "+f"(c[3])
        : "r"(a[0]), "r"(a[1]), "r"(a[2]), "r"(a[3]), "r"(b[0]), "r"(b[1]));
}

// ---------------------------------------------------------------------------
// Kernel 1: per-node LayerNorm, output rounded to tf32
// ---------------------------------------------------------------------------
__global__ __launch_bounds__(256) void node_ln_kernel(const float* __restrict__ x,
                                                      const float* __restrict__ gamma,
                                                      const float* __restrict__ beta) {
    int row = blockIdx.x * 8 + (threadIdx.x >> 5);
    if (row >= N_NODES) return;
    int lane = threadIdx.x & 31;
    float4 v = ((const float4*)(x + (size_t)row * NODE_DIM))[lane];
    float s  = v.x + v.y + v.z + v.w;
    float ss = v.x*v.x + v.y*v.y + v.z*v.z + v.w*v.w;
    #pragma unroll
    for (int o = 16; o; o >>= 1) {
        s  += __shfl_xor_sync(0xffffffffu, s,  o);
        ss += __shfl_xor_sync(0xffffffffu, ss, o);
    }
    float mu  = s * (1.0f/128.0f);
    float inv = rsqrtf(ss * (1.0f/128.0f) - mu*mu + EPS);
    float4 g = ((const float4*)gamma)[lane];
    float4 b = ((const float4*)beta)[lane];
    float4 o4;
    o4.x = tf32r((v.x-mu)*inv*g.x + b.x);
    o4.y = tf32r((v.y-mu)*inv*g.y + b.y);
    o4.z = tf32r((v.z-mu)*inv*g.z + b.z);
    o4.w = tf32r((v.w-mu)*inv*g.w + b.w);
    ((float4*)(g_xn + (size_t)row * NODE_DIM))[lane] = o4;
}

// ---------------------------------------------------------------------------
// Kernel 2: round W to tf32
// ---------------------------------------------------------------------------
__global__ __launch_bounds__(256) void w_prep_kernel(const float* __restrict__ W) {
    int idx = blockIdx.x * 256 + threadIdx.x;
    if (idx < IN_DIM * OUT_DIM) g_wc[idx] = tf32r(W[idx]);
}

// ---------------------------------------------------------------------------
// Kernel 3: mma.sync tf32 GEMM (128 x 256 x 384) + fused gated-residual + LN
// ---------------------------------------------------------------------------
__global__ __launch_bounds__(512, 1) void edge_kernel(const int*   __restrict__ ei,
                                                      const float* __restrict__ ea,
                                                      const float* __restrict__ bias,
                                                      const float* __restrict__ eg,
                                                      const float* __restrict__ eb,
                                                      float* __restrict__ out,
                                                      int E) {
    extern __shared__ float sm[];
    const uint32_t smb = (uint32_t)__cvta_generic_to_shared(sm);

    const int tid  = threadIdx.x;
    const int lane = tid & 31;
    const int wid  = tid >> 5;
    const int wm   = wid & 3;          // 4 M-blocks of 32
    const int wn   = wid >> 2;         // 4 N-blocks of 64
    const int qr   = lane >> 2;
    const int qc   = lane & 3;

    const int e0 = blockIdx.x * TILE_M;
    const int ne = min(TILE_M, E - e0);

    int*   sN_s = (int*)(sm + SM_SN);
    int*   dN_s = (int*)(sm + SM_DN);

    if (tid < TILE_M) {
        int e = e0 + min(tid, ne - 1);
        sN_s[tid] = ei[e];
        dN_s[tid] = ei[E + e];
    }
    if (tid < 64) ((float4*)(sm + SM_BIAS))[tid] = ((const float4*)bias)[tid];
    __syncthreads();

    // -------- cp.async issue for chunk i --------
    auto issue = [&](int i) {
        // A: 128 rows x 32 floats (8 float4 per row) = 1024 float4
        #pragma unroll
        for (int it = 0; it < 2; it++) {
            int idx = tid + 512 * it;
            int row = idx >> 3, c4 = idx & 7;
            const float* src;
            if (i < 4)       src = g_xn + (size_t)sN_s[row] * NODE_DIM + i * KC;
            else if (i < 8)  src = g_xn + (size_t)dN_s[row] * NODE_DIM + (i - 4) * KC;
            else             src = ea + (size_t)min(e0 + row, E - 1) * NODE_DIM + (i - 8) * KC;
            uint32_t dst = smb + (((i & 1) ? SM_A1 : SM_A0) + row * A_STRIDE + c4 * 4) * 4;
            cp16(dst, src + c4 * 4);
        }
        // B: 32 rows x 256 floats (64 float4 per row) = 2048 float4
        const float* Wb = g_wc + (size_t)i * KC * OUT_DIM;
        #pragma unroll
        for (int it = 0; it < 4; it++) {
            int idx = tid + 512 * it;
            int k = idx >> 6, c4 = idx & 63;
            uint32_t dst = smb + (((i & 1) ? SM_B1 : SM_B0) + k * B_STRIDE + c4 * 4) * 4;
            cp16(dst, Wb + k * OUT_DIM + c4 * 4);
        }
        asm volatile("cp.async.commit_group;");
    };

    float acc[2][8][4];
    #pragma unroll
    for (int mt = 0; mt < 2; mt++)
        #pragma unroll
        for (int nt = 0; nt < 8; nt++)
            #pragma unroll
            for (int q = 0; q < 4; q++) acc[mt][nt][q] = 0.f;

    issue(0);

    #pragma unroll 1
    for (int i = 0; i < NCH; i++) {
        if (i + 1 < NCH) {
            issue(i + 1);
            asm volatile("cp.async.wait_group 1;");
        } else {
            asm volatile("cp.async.wait_group 0;");
        }
        __syncthreads();

        const float* Ab = sm + ((i & 1) ? SM_A1 : SM_A0);
        const float* Bb = sm + ((i & 1) ? SM_B1 : SM_B0);

        #pragma unroll
        for (int ks = 0; ks < 4; ks++) {
            const int kb = ks * 8;
            uint32_t a[2][4];
            #pragma unroll
            for (int mt = 0; mt < 2; mt++) {
                int r0 = wm * 32 + mt * 16 + qr;
                a[mt][0] = __float_as_uint(Ab[r0 * A_STRIDE + kb + qc]);
                a[mt][1] = __float_as_uint(Ab[(r0 + 8) * A_STRIDE + kb + qc]);
                a[mt][2] = __float_as_uint(Ab[r0 * A_STRIDE + kb + qc + 4]);
                a[mt][3] = __float_as_uint(Ab[(r0 + 8) * A_STRIDE + kb + qc + 4]);
            }
            uint32_t b[8][2];
            #pragma unroll
            for (int nt = 0; nt < 8; nt++) {
                int n = wn * 64 + nt * 8 + qr;
                b[nt][0] = __float_as_uint(Bb[(kb + qc) * B_STRIDE + n]);
                b[nt][1] = __float_as_uint(Bb[(kb + qc + 4) * B_STRIDE + n]);
            }
            #pragma unroll
            for (int mt = 0; mt < 2; mt++)
                #pragma unroll
                for (int nt = 0; nt < 8; nt++)
                    mma_tf32(acc[mt][nt], a[mt], b[nt]);
        }
        __syncthreads();
    }

    // -------- fragments -> raw smem with bias + relu --------
    {
        float* raw = sm + SM_RAW;
        const float* bs = sm + SM_BIAS;
        #pragma unroll
        for (int mt = 0; mt < 2; mt++) {
            #pragma unroll
            for (int nt = 0; nt < 8; nt++) {
                int r0 = wm * 32 + mt * 16 + qr;
                int c0 = wn * 64 + nt * 8 + 2 * qc;
                raw[r0 * R_STRIDE + c0]           = fmaxf(acc[mt][nt][0] + bs[c0],     0.f);
                raw[r0 * R_STRIDE + c0 + 1]       = fmaxf(acc[mt][nt][1] + bs[c0 + 1], 0.f);
                raw[(r0 + 8) * R_STRIDE + c0]     = fmaxf(acc[mt][nt][2] + bs[c0],     0.f);
                raw[(r0 + 8) * R_STRIDE + c0 + 1] = fmaxf(acc[mt][nt][3] + bs[c0 + 1], 0.f);
            }
        }
    }
    __syncthreads();

    // -------- pass 1: gated residual + LN stats (thread per edge row) --------
    if (tid < TILE_M) {
        int r = tid;
        float* row = sm + SM_RAW + r * R_STRIDE;
        const float4* ear = (const float4*)(ea + (size_t)min(e0 + r, E - 1) * NODE_DIM);
        float s = 0.f, ss = 0.f;
        #pragma unroll
        for (int j4 = 0; j4 < 32; j4++) {
            float4 eav = ear[j4];
            float ev[4] = {eav.x, eav.y, eav.z, eav.w};
            #pragma unroll
            for (int q = 0; q < 4; q++) {
                int j = j4 * 4 + q;
                float d = row[j];
                float g = row[128 + j];
                float sg = 1.0f / (1.0f + __expf(-g));
                float o = ev[q] + sg * d;
                row[j] = o;
                s += o; ss += o * o;
            }
        }
        float mu  = s * (1.0f / 128.0f);
        float inv = rsqrtf(ss * (1.0f / 128.0f) - mu * mu + EPS);
        sm[SM_MU + r]  = mu;
        sm[SM_INV + r] = inv;
    }
    __syncthreads();

    // -------- pass 2: normalize + coalesced float4 writes --------
    {
        float4 g4 = ((const float4*)eg)[lane];
        float4 b4 = ((const float4*)eb)[lane];
        #pragma unroll
        for (int rr = 0; rr < 8; rr++) {
            int r = wid * 8 + rr;
            if (r < ne) {
                const float* row = sm + SM_RAW + r * R_STRIDE + lane * 4;
                float m  = sm[SM_MU + r];
                float iv = sm[SM_INV + r];
                float4 o;
                o.x = (row[0] - m) * iv * g4.x + b4.x;
                o.y = (row[1] - m) * iv * g4.y + b4.y;
                o.z = (row[2] - m) * iv * g4.z + b4.z;
                o.w = (row[3] - m) * iv * g4.w + b4.w;
                ((float4*)(out + (size_t)(e0 + r) * 128))[lane] = o;
            }
        }
    }
}

// ---------------------------------------------------------------------------
extern "C" void kernel_launch(void* const* d_in, const int* in_sizes, int n_in,
                              void* d_out, int out_size) {
    const float* x  = (const float*)d_in[0];
    const int*   ei = (const int*)  d_in[1];
    const float* ea = (const float*)d_in[2];
    const float* W  = (const float*)d_in[3];
    const float* b  = (const float*)d_in[4];
    const float* ng = (const float*)d_in[5];
    const float* nb = (const float*)d_in[6];
    const float* eg = (const float*)d_in[7];
    const float* eb = (const float*)d_in[8];
    float* out = (float*)d_out;

    int E = in_sizes[2] / NODE_DIM;   // 500000

    node_ln_kernel<<<(N_NODES + 7) / 8, 256>>>(x, ng, nb);
    w_prep_kernel<<<(IN_DIM * OUT_DIM + 255) / 256, 256>>>(W);

    cudaFuncSetAttribute(edge_kernel, cudaFuncAttributeMaxDynamicSharedMemorySize, SMEM_BYTES);
    edge_kernel<<<(E + TILE_M - 1) / TILE_M, 512, SMEM_BYTES>>>(ei, ea, b, eg, eb, out, E);
}

// round 5
// speedup vs baseline: 4.4398x; 1.6100x over previous
#include <cuda_runtime.h>
#include <math.h>
#include <stdint.h>

#define N_NODES   50000
#define NODE_DIM  128
#define IN_DIM    384
#define OUT_DIM   256
#define EPS       1e-5f
#define TILE_M    128
#define KC        32
#define NCH       12
#define NSTAGE    3

// ---- static device scratch (no allocs) ----
__device__ float g_xn[(size_t)N_NODES * NODE_DIM];   // node-LN output, tf32-rounded
__device__ float g_wc[(size_t)IN_DIM * OUT_DIM];     // W tf32-rounded

// ---- smem layout (float offsets) ----
#define A_STRIDE 36
#define B_STRIDE 264
#define R_STRIDE 257
#define SM_A(s)  ((s) * (TILE_M * A_STRIDE))                 // 3 x 4608
#define SM_B(s)  (NSTAGE * TILE_M * A_STRIDE + (s) * (KC * B_STRIDE))  // 3 x 8448
#define SM_RAW   0
#define SM_MISC  (NSTAGE * (TILE_M * A_STRIDE + KC * B_STRIDE))   // 39168
#define SM_BIAS  (SM_MISC)
#define SM_SN    (SM_MISC + 256)
#define SM_DN    (SM_MISC + 384)
#define SM_MU    (SM_MISC + 512)
#define SM_INV   (SM_MISC + 640)
#define SMEM_FLOATS (SM_MISC + 768)
#define SMEM_BYTES  (SMEM_FLOATS * 4)     // 159744 B

static __device__ __forceinline__ float tf32r(float x) {
    uint32_t t;
    asm("cvt.rna.tf32.f32 %0, %1;" : "=r"(t) : "f"(x));
    return __uint_as_float(t);
}
static __device__ __forceinline__ void cp16(uint32_t dst, const void* src) {
    asm volatile("cp.async.cg.shared.global [%0], [%1], 16;" :: "r"(dst), "l"(src));
}
static __device__ __forceinline__ void mma_tf32(float* c, const uint32_t* a, const uint32_t* b) {
    asm volatile(
        "mma.sync.aligned.m16n8k8.row.col.f32.tf32.tf32.f32 "
        "{%0,%1,%2,%3}, {%4,%5,%6,%7}, {%8,%9}, {%0,%1,%2,%3};"
        : "+f"(c[0]), "+f"(c[1]), "+f"(c[2]), "+f"(c[3])
        : "r"(a[0]), "r"(a[1]), "r"(a[2]), "r"(a[3]), "r"(b[0]), "r"(b[1]));
}

// ---------------------------------------------------------------------------
// Kernel 1 (merged prep): blocks [0,6250) node LayerNorm; rest round W to tf32
// ---------------------------------------------------------------------------
#define LN_BLOCKS ((N_NODES + 7) / 8)
#define W_BLOCKS  ((IN_DIM * OUT_DIM + 255) / 256)
__global__ __launch_bounds__(256) void prep_kernel(const float* __restrict__ x,
                                                   const float* __restrict__ gamma,
                                                   const float* __restrict__ beta,
                                                   const float* __restrict__ W) {
    if (blockIdx.x >= LN_BLOCKS) {
        int idx = (blockIdx.x - LN_BLOCKS) * 256 + threadIdx.x;
        if (idx < IN_DIM * OUT_DIM) g_wc[idx] = tf32r(W[idx]);
        return;
    }
    int row = blockIdx.x * 8 + (threadIdx.x >> 5);
    if (row >= N_NODES) return;
    int lane = threadIdx.x & 31;
    float4 v = ((const float4*)(x + (size_t)row * NODE_DIM))[lane];
    float s  = v.x + v.y + v.z + v.w;
    float ss = v.x*v.x + v.y*v.y + v.z*v.z + v.w*v.w;
    #pragma unroll
    for (int o = 16; o; o >>= 1) {
        s  += __shfl_xor_sync(0xffffffffu, s,  o);
        ss += __shfl_xor_sync(0xffffffffu, ss, o);
    }
    float mu  = s * (1.0f/128.0f);
    float inv = rsqrtf(ss * (1.0f/128.0f) - mu*mu + EPS);
    float4 g = ((const float4*)gamma)[lane];
    float4 b = ((const float4*)beta)[lane];
    float4 o4;
    o4.x = tf32r((v.x-mu)*inv*g.x + b.x);
    o4.y = tf32r((v.y-mu)*inv*g.y + b.y);
    o4.z = tf32r((v.z-mu)*inv*g.z + b.z);
    o4.w = tf32r((v.w-mu)*inv*g.w + b.w);
    ((float4*)(g_xn + (size_t)row * NODE_DIM))[lane] = o4;
}

// ---------------------------------------------------------------------------
// Kernel 2: mma.sync tf32 GEMM (128 x 256 x 384), 3-stage cp.async,
//           warp tile 64x64, fused gated-residual + edge LayerNorm
// ---------------------------------------------------------------------------
__global__ __launch_bounds__(256, 1) void edge_kernel(const int*   __restrict__ ei,
                                                      const float* __restrict__ ea,
                                                      const float* __restrict__ bias,
                                                      const float* __restrict__ eg,
                                                      const float* __restrict__ eb,
                                                      float* __restrict__ out,
                                                      int E) {
    extern __shared__ float sm[];
    const uint32_t smb = (uint32_t)__cvta_generic_to_shared(sm);

    const int tid  = threadIdx.x;
    const int lane = tid & 31;
    const int wid  = tid >> 5;
    const int wm   = wid & 1;          // 2 M-blocks of 64
    const int wn   = wid >> 1;         // 4 N-blocks of 64
    const int qr   = lane >> 2;
    const int qc   = lane & 3;

    const int e0 = blockIdx.x * TILE_M;
    const int ne = min(TILE_M, E - e0);

    int* sN_s = (int*)(sm + SM_SN);
    int* dN_s = (int*)(sm + SM_DN);

    if (tid < TILE_M) {
        int e = e0 + min(tid, ne - 1);
        sN_s[tid] = ei[e];
        dN_s[tid] = ei[E + e];
    }
    if (tid < 64) ((float4*)(sm + SM_BIAS))[tid] = ((const float4*)bias)[tid];
    __syncthreads();

    // -------- cp.async issue for chunk i into stage i%3 --------
    auto issue = [&](int i) {
        const int st = i % NSTAGE;
        #pragma unroll
        for (int it = 0; it < 4; it++) {              // A: 1024 float4
            int idx = tid + 256 * it;
            int row = idx >> 3, c4 = idx & 7;
            const float* src;
            if (i < 4)       src = g_xn + (size_t)sN_s[row] * NODE_DIM + i * KC;
            else if (i < 8)  src = g_xn + (size_t)dN_s[row] * NODE_DIM + (i - 4) * KC;
            else             src = ea + (size_t)min(e0 + row, E - 1) * NODE_DIM + (i - 8) * KC;
            cp16(smb + (SM_A(st) + row * A_STRIDE + c4 * 4) * 4, src + c4 * 4);
        }
        const float* Wb = g_wc + (size_t)i * KC * OUT_DIM;
        #pragma unroll
        for (int it = 0; it < 8; it++) {              // B: 2048 float4
            int idx = tid + 256 * it;
            int k = idx >> 6, c4 = idx & 63;
            cp16(smb + (SM_B(st) + k * B_STRIDE + c4 * 4) * 4, Wb + k * OUT_DIM + c4 * 4);
        }
        asm volatile("cp.async.commit_group;");
    };

    float acc[4][8][4];
    #pragma unroll
    for (int mt = 0; mt < 4; mt++)
        #pragma unroll
        for (int nt = 0; nt < 8; nt++)
            #pragma unroll
            for (int q = 0; q < 4; q++) acc[mt][nt][q] = 0.f;

    issue(0);
    issue(1);

    #pragma unroll 1
    for (int i = 0; i < NCH; i++) {
        if (i == NCH - 1) asm volatile("cp.async.wait_group 0;");
        else              asm volatile("cp.async.wait_group 1;");
        __syncthreads();   // single barrier per chunk: data visible + prev compute done

        const int st = i % NSTAGE;
        const float* Ab = sm + SM_A(st);
        const float* Bb = sm + SM_B(st);

        #pragma unroll
        for (int ks = 0; ks < 4; ks++) {
            const int kb = ks * 8;
            uint32_t a[4][4];
            #pragma unroll
            for (int mt = 0; mt < 4; mt++) {
                int r0 = wm * 64 + mt * 16 + qr;
                a[mt][0] = __float_as_uint(Ab[r0 * A_STRIDE + kb + qc]);
                a[mt][1] = __float_as_uint(Ab[(r0 + 8) * A_STRIDE + kb + qc]);
                a[mt][2] = __float_as_uint(Ab[r0 * A_STRIDE + kb + qc + 4]);
                a[mt][3] = __float_as_uint(Ab[(r0 + 8) * A_STRIDE + kb + qc + 4]);
            }
            uint32_t b[8][2];
            #pragma unroll
            for (int nt = 0; nt < 8; nt++) {
                int n = wn * 64 + nt * 8 + qr;
                b[nt][0] = __float_as_uint(Bb[(kb + qc) * B_STRIDE + n]);
                b[nt][1] = __float_as_uint(Bb[(kb + qc + 4) * B_STRIDE + n]);
            }
            #pragma unroll
            for (int mt = 0; mt < 4; mt++)
                #pragma unroll
                for (int nt = 0; nt < 8; nt++)
                    mma_tf32(acc[mt][nt], a[mt], b[nt]);
        }

        if (i + 2 < NCH) issue(i + 2);   // targets stage (i-1)%3; safe past this iter's barrier
    }
    __syncthreads();   // all warps done reading stages before raw aliases them

    // -------- fragments -> raw smem with bias + relu --------
    {
        float* raw = sm + SM_RAW;
        const float* bs = sm + SM_BIAS;
        #pragma unroll
        for (int mt = 0; mt < 4; mt++) {
            #pragma unroll
            for (int nt = 0; nt < 8; nt++) {
                int r0 = wm * 64 + mt * 16 + qr;
                int c0 = wn * 64 + nt * 8 + 2 * qc;
                raw[r0 * R_STRIDE + c0]           = fmaxf(acc[mt][nt][0] + bs[c0],     0.f);
                raw[r0 * R_STRIDE + c0 + 1]       = fmaxf(acc[mt][nt][1] + bs[c0 + 1], 0.f);
                raw[(r0 + 8) * R_STRIDE + c0]     = fmaxf(acc[mt][nt][2] + bs[c0],     0.f);
                raw[(r0 + 8) * R_STRIDE + c0 + 1] = fmaxf(acc[mt][nt][3] + bs[c0 + 1], 0.f);
            }
        }
    }
    __syncthreads();

    // -------- pass 1: gated residual + LN stats (thread per edge row) --------
    if (tid < TILE_M) {
        int r = tid;
        float* row = sm + SM_RAW + r * R_STRIDE;
        const float4* ear = (const float4*)(ea + (size_t)min(e0 + r, E - 1) * NODE_DIM);
        float s = 0.f, ss = 0.f;
        #pragma unroll
        for (int j4 = 0; j4 < 32; j4++) {
            float4 eav = ear[j4];
            float ev[4] = {eav.x, eav.y, eav.z, eav.w};
            #pragma unroll
            for (int q = 0; q < 4; q++) {
                int j = j4 * 4 + q;
                float d = row[j];
                float g = row[128 + j];
                float sg = 1.0f / (1.0f + __expf(-g));
                float o = ev[q] + sg * d;
                row[j] = o;
                s += o; ss += o * o;
            }
        }
        float mu  = s * (1.0f / 128.0f);
        float inv = rsqrtf(ss * (1.0f / 128.0f) - mu * mu + EPS);
        sm[SM_MU + r]  = mu;
        sm[SM_INV + r] = inv;
    }
    __syncthreads();

    // -------- pass 2: normalize + coalesced float4 writes --------
    {
        float4 g4 = ((const float4*)eg)[lane];
        float4 b4 = ((const float4*)eb)[lane];
        #pragma unroll
        for (int rr = 0; rr < 16; rr++) {
            int r = wid * 16 + rr;
            if (r < ne) {
                const float* row = sm + SM_RAW + r * R_STRIDE + lane * 4;
                float m  = sm[SM_MU + r];
                float iv = sm[SM_INV + r];
                float4 o;
                o.x = (row[0] - m) * iv * g4.x + b4.x;
                o.y = (row[1] - m) * iv * g4.y + b4.y;
                o.z = (row[2] - m) * iv * g4.z + b4.z;
                o.w = (row[3] - m) * iv * g4.w + b4.w;
                ((float4*)(out + (size_t)(e0 + r) * 128))[lane] = o;
            }
        }
    }
}

// ---------------------------------------------------------------------------
extern "C" void kernel_launch(void* const* d_in, const int* in_sizes, int n_in,
                              void* d_out, int out_size) {
    const float* x  = (const float*)d_in[0];
    const int*   ei = (const int*)  d_in[1];
    const float* ea = (const float*)d_in[2];
    const float* W  = (const float*)d_in[3];
    const float* b  = (const float*)d_in[4];
    const float* ng = (const float*)d_in[5];
    const float* nb = (const float*)d_in[6];
    const float* eg = (const float*)d_in[7];
    const float* eb = (const float*)d_in[8];
    float* out = (float*)d_out;

    int E = in_sizes[2] / NODE_DIM;   // 500000

    prep_kernel<<<LN_BLOCKS + W_BLOCKS, 256>>>(x, ng, nb, W);

    cudaFuncSetAttribute(edge_kernel, cudaFuncAttributeMaxDynamicSharedMemorySize, SMEM_BYTES);
    edge_kernel<<<(E + TILE_M - 1) / TILE_M, 256, SMEM_BYTES>>>(ei, ea, b, eg, eb, out, E);
}

// round 6
// speedup vs baseline: 4.9934x; 1.1247x over previous
#include <cuda_runtime.h>
#include <cuda_bf16.h>
#include <math.h>
#include <stdint.h>

#define N_NODES   50000
#define NODE_DIM  128
#define IN_DIM    384
#define OUT_DIM   256
#define EPS       1e-5f
#define TILE_M    128
#define KC        32
#define NCH       12
#define NSTAGE    3
#define E_MAX     500000

// ---- static device scratch (no allocs) ----
__device__ __nv_bfloat16 g_xn[(size_t)N_NODES * NODE_DIM];   // LN'd nodes, bf16
__device__ __nv_bfloat16 g_wb[(size_t)IN_DIM * OUT_DIM];     // W bf16, [k][n]
__device__ __nv_bfloat16 g_eb[(size_t)E_MAX * NODE_DIM];     // edge_attr bf16

// ---- smem byte layout ----
#define A_STRIDE   40                           // bf16 units (80 B rows: conflict-free ldmatrix)
#define B_STRIDE   264                          // bf16 units (528 B rows: conflict-free)
#define A_OFF(s)   ((s) * (TILE_M * A_STRIDE * 2))            // 3 x 10240 B
#define B_OFF(s)   (NSTAGE * TILE_M * A_STRIDE * 2 + (s) * (KC * B_STRIDE * 2))  // 3 x 16896 B
#define R_STRIDE   257                          // float units
#define RAW_BYTES  (TILE_M * R_STRIDE * 4)      // 131584 B (aliases mainloop bufs)
#define MISC_F     (RAW_BYTES / 4)              // float index of misc region
#define SM_BIAS    (MISC_F)
#define SM_SN      (MISC_F + 256)
#define SM_DN      (MISC_F + 384)
#define SM_MU      (MISC_F + 512)
#define SM_INV     (MISC_F + 640)
#define SMEM_BYTES (RAW_BYTES + 768 * 4)        // 134656 B

static __device__ __forceinline__ void cp16(uint32_t dst, const void* src) {
    asm volatile("cp.async.cg.shared.global [%0], [%1], 16;" :: "r"(dst), "l"(src));
}
static __device__ __forceinline__ void ldsm4(uint32_t* r, uint32_t addr) {
    asm volatile("ldmatrix.sync.aligned.m8n8.x4.shared.b16 {%0,%1,%2,%3}, [%4];"
                 : "=r"(r[0]), "=r"(r[1]), "=r"(r[2]), "=r"(r[3]) : "r"(addr));
}
static __device__ __forceinline__ void ldsm4t(uint32_t* r, uint32_t addr) {
    asm volatile("ldmatrix.sync.aligned.m8n8.x4.trans.shared.b16 {%0,%1,%2,%3}, [%4];"
                 : "=r"(r[0]), "=r"(r[1]), "=r"(r[2]), "=r"(r[3]) : "r"(addr));
}
static __device__ __forceinline__ void mma_bf16(float* c, const uint32_t* a, const uint32_t* b) {
    asm volatile(
        "mma.sync.aligned.m16n8k16.row.col.f32.bf16.bf16.f32 "
        "{%0,%1,%2,%3}, {%4,%5,%6,%7}, {%8,%9}, {%0,%1,%2,%3};"
        : "+f"(c[0]), "+f"(c[1]), "+f"(c[2]), "+f"(c[3])
        : "r"(a[0]), "r"(a[1]), "r"(a[2]), "r"(a[3]), "r"(b[0]), "r"(b[1]));
}

// ---------------------------------------------------------------------------
// Kernel 1 (merged prep): node LN -> bf16 | W -> bf16 | edge_attr -> bf16
// ---------------------------------------------------------------------------
#define LN_BLOCKS ((N_NODES + 7) / 8)
#define W_BLOCKS  ((IN_DIM * OUT_DIM + 255) / 256)
__global__ __launch_bounds__(256) void prep_kernel(const float* __restrict__ x,
                                                   const float* __restrict__ gamma,
                                                   const float* __restrict__ beta,
                                                   const float* __restrict__ W,
                                                   const float* __restrict__ ea,
                                                   int E) {
    int b = blockIdx.x;
    if (b < LN_BLOCKS) {
        int row = b * 8 + (threadIdx.x >> 5);
        if (row >= N_NODES) return;
        int lane = threadIdx.x & 31;
        float4 v = ((const float4*)(x + (size_t)row * NODE_DIM))[lane];
        float s  = v.x + v.y + v.z + v.w;
        float ss = v.x*v.x + v.y*v.y + v.z*v.z + v.w*v.w;
        #pragma unroll
        for (int o = 16; o; o >>= 1) {
            s  += __shfl_xor_sync(0xffffffffu, s,  o);
            ss += __shfl_xor_sync(0xffffffffu, ss, o);
        }
        float mu  = s * (1.0f/128.0f);
        float inv = rsqrtf(ss * (1.0f/128.0f) - mu*mu + EPS);
        float4 g = ((const float4*)gamma)[lane];
        float4 bb = ((const float4*)beta)[lane];
        __nv_bfloat162 h0 = {__float2bfloat16_rn((v.x-mu)*inv*g.x + bb.x),
                             __float2bfloat16_rn((v.y-mu)*inv*g.y + bb.y)};
        __nv_bfloat162 h1 = {__float2bfloat16_rn((v.z-mu)*inv*g.z + bb.z),
                             __float2bfloat16_rn((v.w-mu)*inv*g.w + bb.w)};
        __nv_bfloat162* dst = (__nv_bfloat162*)(g_xn + (size_t)row * NODE_DIM);
        dst[2*lane]   = h0;
        dst[2*lane+1] = h1;
    } else if (b < LN_BLOCKS + W_BLOCKS) {
        int idx = (b - LN_BLOCKS) * 256 + threadIdx.x;
        if (idx < IN_DIM * OUT_DIM) g_wb[idx] = __float2bfloat16_rn(W[idx]);
    } else {
        int idx = (b - LN_BLOCKS - W_BLOCKS) * 256 + threadIdx.x;   // one float4 each
        if (idx < E * (NODE_DIM / 4)) {
            float4 v = ((const float4*)ea)[idx];
            __nv_bfloat162 h0 = {__float2bfloat16_rn(v.x), __float2bfloat16_rn(v.y)};
            __nv_bfloat162 h1 = {__float2bfloat16_rn(v.z), __float2bfloat16_rn(v.w)};
            ((__nv_bfloat162*)g_eb)[2*idx]   = h0;
            ((__nv_bfloat162*)g_eb)[2*idx+1] = h1;
        }
    }
}

// ---------------------------------------------------------------------------
// Kernel 2: bf16 mma.sync GEMM (128 x 256 x 384), ldmatrix fragments,
//           3-stage cp.async, fused gated-residual + edge LayerNorm
// ---------------------------------------------------------------------------
__global__ __launch_bounds__(256, 1) void edge_kernel(const int*   __restrict__ ei,
                                                      const float* __restrict__ ea,
                                                      const float* __restrict__ bias,
                                                      const float* __restrict__ eg,
                                                      const float* __restrict__ eb,
                                                      float* __restrict__ out,
                                                      int E) {
    extern __shared__ __align__(16) char smc[];
    float* sm = (float*)smc;
    const uint32_t smb = (uint32_t)__cvta_generic_to_shared(smc);

    const int tid  = threadIdx.x;
    const int lane = tid & 31;
    const int wid  = tid >> 5;
    const int wm   = wid & 1;          // 2 M-blocks of 64
    const int wn   = wid >> 1;         // 4 N-blocks of 64
    const int qr   = lane >> 2;
    const int qc   = lane & 3;

    const int e0 = blockIdx.x * TILE_M;
    const int ne = min(TILE_M, E - e0);

    int* sN_s = (int*)(sm + SM_SN);
    int* dN_s = (int*)(sm + SM_DN);

    if (tid < TILE_M) {
        int e = e0 + min(tid, ne - 1);
        sN_s[tid] = ei[e];
        dN_s[tid] = ei[E + e];
    }
    if (tid < 64) ((float4*)(sm + SM_BIAS))[tid] = ((const float4*)bias)[tid];
    __syncthreads();

    // -------- cp.async issue for chunk i into stage i%3 --------
    auto issue = [&](int i) {
        const int st = i % NSTAGE;
        #pragma unroll
        for (int it = 0; it < 2; it++) {              // A: 512 cp16 (128 rows x 4)
            int idx = tid + 256 * it;
            int row = idx >> 2, c = idx & 3;
            const __nv_bfloat16* src;
            if (i < 4)       src = g_xn + (size_t)sN_s[row] * NODE_DIM + i * KC;
            else if (i < 8)  src = g_xn + (size_t)dN_s[row] * NODE_DIM + (i - 4) * KC;
            else             src = g_eb + (size_t)min(e0 + row, E - 1) * NODE_DIM + (i - 8) * KC;
            cp16(smb + A_OFF(st) + (row * A_STRIDE + c * 8) * 2, src + c * 8);
        }
        const __nv_bfloat16* Wb = g_wb + (size_t)i * KC * OUT_DIM;
        #pragma unroll
        for (int it = 0; it < 4; it++) {              // B: 1024 cp16 (32 rows x 32)
            int idx = tid + 256 * it;
            int k = idx >> 5, c = idx & 31;
            cp16(smb + B_OFF(st) + (k * B_STRIDE + c * 8) * 2, Wb + k * OUT_DIM + c * 8);
        }
        asm volatile("cp.async.commit_group;");
    };

    float acc[4][8][4];
    #pragma unroll
    for (int mt = 0; mt < 4; mt++)
        #pragma unroll
        for (int nt = 0; nt < 8; nt++)
            #pragma unroll
            for (int q = 0; q < 4; q++) acc[mt][nt][q] = 0.f;

    // ldmatrix lane-address components (bf16 units)
    const int a_row = (lane & 7) + ((lane >> 3) & 1) * 8;   // 0..15 row within m16
    const int a_ks  = (lane >> 4) * 8;                      // k half-select
    const int b_krw = (lane & 7) + ((lane >> 3) & 1) * 8;   // 0..15 row within k16
    const int b_ns  = (lane >> 4) * 8;                      // n half-select

    issue(0);
    issue(1);

    #pragma unroll 1
    for (int i = 0; i < NCH; i++) {
        if (i == NCH - 1) asm volatile("cp.async.wait_group 0;");
        else              asm volatile("cp.async.wait_group 1;");
        __syncthreads();

        const int st = i % NSTAGE;
        const uint32_t Ab = smb + A_OFF(st);
        const uint32_t Bb = smb + B_OFF(st);

        #pragma unroll
        for (int ks = 0; ks < 2; ks++) {
            const int k0 = ks * 16;
            uint32_t a[4][4];
            #pragma unroll
            for (int mt = 0; mt < 4; mt++)
                ldsm4(a[mt], Ab + ((wm * 64 + mt * 16 + a_row) * A_STRIDE + k0 + a_ks) * 2);
            uint32_t bf[4][4];
            #pragma unroll
            for (int ntt = 0; ntt < 4; ntt++)
                ldsm4t(bf[ntt], Bb + ((k0 + b_krw) * B_STRIDE + wn * 64 + ntt * 16 + b_ns) * 2);
            #pragma unroll
            for (int mt = 0; mt < 4; mt++)
                #pragma unroll
                for (int nt = 0; nt < 8; nt++)
                    mma_bf16(acc[mt][nt], a[mt], &bf[nt >> 1][(nt & 1) * 2]);
        }

        if (i + 2 < NCH) issue(i + 2);
    }
    __syncthreads();   // all reads of staging done before raw aliases it

    // -------- fragments -> raw smem with bias + relu --------
    {
        float* raw = sm;
        const float* bs = sm + SM_BIAS;
        #pragma unroll
        for (int mt = 0; mt < 4; mt++) {
            #pragma unroll
            for (int nt = 0; nt < 8; nt++) {
                int r0 = wm * 64 + mt * 16 + qr;
                int c0 = wn * 64 + nt * 8 + 2 * qc;
                raw[r0 * R_STRIDE + c0]           = fmaxf(acc[mt][nt][0] + bs[c0],     0.f);
                raw[r0 * R_STRIDE + c0 + 1]       = fmaxf(acc[mt][nt][1] + bs[c0 + 1], 0.f);
                raw[(r0 + 8) * R_STRIDE + c0]     = fmaxf(acc[mt][nt][2] + bs[c0],     0.f);
                raw[(r0 + 8) * R_STRIDE + c0 + 1] = fmaxf(acc[mt][nt][3] + bs[c0 + 1], 0.f);
            }
        }
    }
    __syncthreads();

    // -------- pass 1: gated residual + LN stats (thread per edge row) --------
    if (tid < TILE_M) {
        int r = tid;
        float* row = sm + r * R_STRIDE;
        const float4* ear = (const float4*)(ea + (size_t)min(e0 + r, E - 1) * NODE_DIM);
        float s = 0.f, ss = 0.f;
        #pragma unroll
        for (int j4 = 0; j4 < 32; j4++) {
            float4 eav = ear[j4];
            float ev[4] = {eav.x, eav.y, eav.z, eav.w};
            #pragma unroll
            for (int q = 0; q < 4; q++) {
                int j = j4 * 4 + q;
                float d = row[j];
                float g = row[128 + j];
                float sg = 1.0f / (1.0f + __expf(-g));
                float o = ev[q] + sg * d;
                row[j] = o;
                s += o; ss += o * o;
            }
        }
        float mu  = s * (1.0f / 128.0f);
        float inv = rsqrtf(ss * (1.0f / 128.0f) - mu * mu + EPS);
        sm[SM_MU + r]  = mu;
        sm[SM_INV + r] = inv;
    }
    __syncthreads();

    // -------- pass 2: normalize + coalesced float4 writes --------
    {
        float4 g4 = ((const float4*)eg)[lane];
        float4 b4 = ((const float4*)eb)[lane];
        #pragma unroll
        for (int rr = 0; rr < 16; rr++) {
            int r = wid * 16 + rr;
            if (r < ne) {
                const float* row = sm + r * R_STRIDE + lane * 4;
                float m  = sm[SM_MU + r];
                float iv = sm[SM_INV + r];
                float4 o;
                o.x = (row[0] - m) * iv * g4.x + b4.x;
                o.y = (row[1] - m) * iv * g4.y + b4.y;
                o.z = (row[2] - m) * iv * g4.z + b4.z;
                o.w = (row[3] - m) * iv * g4.w + b4.w;
                ((float4*)(out + (size_t)(e0 + r) * 128))[lane] = o;
            }
        }
    }
}

// ---------------------------------------------------------------------------
extern "C" void kernel_launch(void* const* d_in, const int* in_sizes, int n_in,
                              void* d_out, int out_size) {
    const float* x  = (const float*)d_in[0];
    const int*   ei = (const int*)  d_in[1];
    const float* ea = (const float*)d_in[2];
    const float* W  = (const float*)d_in[3];
    const float* b  = (const float*)d_in[4];
    const float* ng = (const float*)d_in[5];
    const float* nb = (const float*)d_in[6];
    const float* eg = (const float*)d_in[7];
    const float* eb = (const float*)d_in[8];
    float* out = (float*)d_out;

    int E = in_sizes[2] / NODE_DIM;   // 500000

    int ea_blocks = (E * (NODE_DIM / 4) + 255) / 256;
    prep_kernel<<<LN_BLOCKS + W_BLOCKS + ea_blocks, 256>>>(x, ng, nb, W, ea, E);

    cudaFuncSetAttribute(edge_kernel, cudaFuncAttributeMaxDynamicSharedMemorySize, SMEM_BYTES);
    edge_kernel<<<(E + TILE_M - 1) / TILE_M, 256, SMEM_BYTES>>>(ei, ea, b, eg, eb, out, E);
}

// round 7
// speedup vs baseline: 5.0530x; 1.0119x over previous
#include <cuda_runtime.h>
#include <cuda_bf16.h>
#include <math.h>
#include <stdint.h>

#define N_NODES   50000
#define NODE_DIM  128
#define IN_DIM    384
#define OUT_DIM   256
#define EPS       1e-5f
#define TILE_M    128
#define KC        32
#define NCH       12
#define NSTAGE    3
#define E_MAX     500000
#define THREADS   512

// ---- static device scratch (no allocs) ----
__device__ __nv_bfloat16 g_xn[(size_t)N_NODES * NODE_DIM];   // LN'd nodes, bf16
__device__ __nv_bfloat16 g_wb[(size_t)IN_DIM * OUT_DIM];     // W bf16, [k][n]
__device__ __nv_bfloat16 g_eb[(size_t)E_MAX * NODE_DIM];     // edge_attr bf16

// ---- smem byte layout ----
#define A_STRIDE   40                           // bf16 units (80 B rows)
#define B_STRIDE   264                          // bf16 units (528 B rows)
#define A_OFF(s)   ((s) * (TILE_M * A_STRIDE * 2))
#define B_OFF(s)   (NSTAGE * TILE_M * A_STRIDE * 2 + (s) * (KC * B_STRIDE * 2))
#define R_STRIDE   257                          // float units
#define RAW_BYTES  (TILE_M * R_STRIDE * 4)      // 131584 B (aliases mainloop bufs)
#define MISC_F     (RAW_BYTES / 4)
#define SM_BIAS    (MISC_F)
#define SM_SN      (MISC_F + 256)
#define SM_DN      (MISC_F + 384)
#define SM_MU      (MISC_F + 512)
#define SM_INV     (MISC_F + 640)
#define SMEM_BYTES (RAW_BYTES + 768 * 4)        // 134656 B

static __device__ __forceinline__ void cp16(uint32_t dst, const void* src) {
    asm volatile("cp.async.cg.shared.global [%0], [%1], 16;" :: "r"(dst), "l"(src));
}
static __device__ __forceinline__ void ldsm4(uint32_t* r, uint32_t addr) {
    asm volatile("ldmatrix.sync.aligned.m8n8.x4.shared.b16 {%0,%1,%2,%3}, [%4];"
                 : "=r"(r[0]), "=r"(r[1]), "=r"(r[2]), "=r"(r[3]) : "r"(addr));
}
static __device__ __forceinline__ void ldsm4t(uint32_t* r, uint32_t addr) {
    asm volatile("ldmatrix.sync.aligned.m8n8.x4.trans.shared.b16 {%0,%1,%2,%3}, [%4];"
                 : "=r"(r[0]), "=r"(r[1]), "=r"(r[2]), "=r"(r[3]) : "r"(addr));
}
static __device__ __forceinline__ void mma_bf16(float* c, const uint32_t* a, const uint32_t* b) {
    asm volatile(
        "mma.sync.aligned.m16n8k16.row.col.f32.bf16.bf16.f32 "
        "{%0,%1,%2,%3}, {%4,%5,%6,%7}, {%8,%9}, {%0,%1,%2,%3};"
        : "+f"(c[0]), "+f"(c[1]), "+f"(c[2]), "+f"(c[3])
        : "r"(a[0]), "r"(a[1]), "r"(a[2]), "r"(a[3]), "r"(b[0]), "r"(b[1]));
}

// ---------------------------------------------------------------------------
// Kernel 1 (merged prep): node LN -> bf16 | W -> bf16 | edge_attr -> bf16
// ---------------------------------------------------------------------------
#define LN_BLOCKS ((N_NODES + 7) / 8)
#define W_BLOCKS  ((IN_DIM * OUT_DIM + 255) / 256)
__global__ __launch_bounds__(256) void prep_kernel(const float* __restrict__ x,
                                                   const float* __restrict__ gamma,
                                                   const float* __restrict__ beta,
                                                   const float* __restrict__ W,
                                                   const float* __restrict__ ea,
                                                   int E) {
    int b = blockIdx.x;
    if (b < LN_BLOCKS) {
        int row = b * 8 + (threadIdx.x >> 5);
        if (row >= N_NODES) return;
        int lane = threadIdx.x & 31;
        float4 v = ((const float4*)(x + (size_t)row * NODE_DIM))[lane];
        float s  = v.x + v.y + v.z + v.w;
        float ss = v.x*v.x + v.y*v.y + v.z*v.z + v.w*v.w;
        #pragma unroll
        for (int o = 16; o; o >>= 1) {
            s  += __shfl_xor_sync(0xffffffffu, s,  o);
            ss += __shfl_xor_sync(0xffffffffu, ss, o);
        }
        float mu  = s * (1.0f/128.0f);
        float inv = rsqrtf(ss * (1.0f/128.0f) - mu*mu + EPS);
        float4 g = ((const float4*)gamma)[lane];
        float4 bb = ((const float4*)beta)[lane];
        __nv_bfloat162 h0 = {__float2bfloat16_rn((v.x-mu)*inv*g.x + bb.x),
                             __float2bfloat16_rn((v.y-mu)*inv*g.y + bb.y)};
        __nv_bfloat162 h1 = {__float2bfloat16_rn((v.z-mu)*inv*g.z + bb.z),
                             __float2bfloat16_rn((v.w-mu)*inv*g.w + bb.w)};
        __nv_bfloat162* dst = (__nv_bfloat162*)(g_xn + (size_t)row * NODE_DIM);
        dst[2*lane]   = h0;
        dst[2*lane+1] = h1;
    } else if (b < LN_BLOCKS + W_BLOCKS) {
        int idx = (b - LN_BLOCKS) * 256 + threadIdx.x;
        if (idx < IN_DIM * OUT_DIM) g_wb[idx] = __float2bfloat16_rn(W[idx]);
    } else {
        int idx = (b - LN_BLOCKS - W_BLOCKS) * 256 + threadIdx.x;
        if (idx < E * (NODE_DIM / 4)) {
            float4 v = ((const float4*)ea)[idx];
            __nv_bfloat162 h0 = {__float2bfloat16_rn(v.x), __float2bfloat16_rn(v.y)};
            __nv_bfloat162 h1 = {__float2bfloat16_rn(v.z), __float2bfloat16_rn(v.w)};
            ((__nv_bfloat162*)g_eb)[2*idx]   = h0;
            ((__nv_bfloat162*)g_eb)[2*idx+1] = h1;
        }
    }
}

// ---------------------------------------------------------------------------
// Kernel 2: bf16 mma.sync GEMM (128 x 256 x 384), 16 warps, warp tile 32x64,
//           ldmatrix, 3-stage cp.async, fused gated-residual + edge LayerNorm
// ---------------------------------------------------------------------------
__global__ __launch_bounds__(THREADS, 1) void edge_kernel(const int*   __restrict__ ei,
                                                          const float* __restrict__ ea,
                                                          const float* __restrict__ bias,
                                                          const float* __restrict__ eg,
                                                          const float* __restrict__ eb,
                                                          float* __restrict__ out,
                                                          int E) {
    extern __shared__ __align__(16) char smc[];
    float* sm = (float*)smc;
    const uint32_t smb = (uint32_t)__cvta_generic_to_shared(smc);

    const int tid  = threadIdx.x;
    const int lane = tid & 31;
    const int wid  = tid >> 5;
    const int wm   = wid & 3;          // 4 M-blocks of 32
    const int wn   = wid >> 2;         // 4 N-blocks of 64
    const int qr   = lane >> 2;
    const int qc   = lane & 3;

    const int e0 = blockIdx.x * TILE_M;
    const int ne = min(TILE_M, E - e0);

    int* sN_s = (int*)(sm + SM_SN);
    int* dN_s = (int*)(sm + SM_DN);

    if (tid < TILE_M) {
        int e = e0 + min(tid, ne - 1);
        sN_s[tid] = ei[e];
        dN_s[tid] = ei[E + e];
    }
    if (tid < 64) ((float4*)(sm + SM_BIAS))[tid] = ((const float4*)bias)[tid];
    __syncthreads();

    // -------- cp.async issue for chunk i into stage i%3 --------
    auto issue = [&](int i) {
        const int st = i % NSTAGE;
        {                                             // A: 512 cp16 (128 rows x 4)
            int row = tid >> 2, c = tid & 3;
            const __nv_bfloat16* src;
            if (i < 4)       src = g_xn + (size_t)sN_s[row] * NODE_DIM + i * KC;
            else if (i < 8)  src = g_xn + (size_t)dN_s[row] * NODE_DIM + (i - 4) * KC;
            else             src = g_eb + (size_t)min(e0 + row, E - 1) * NODE_DIM + (i - 8) * KC;
            cp16(smb + A_OFF(st) + (row * A_STRIDE + c * 8) * 2, src + c * 8);
        }
        const __nv_bfloat16* Wb = g_wb + (size_t)i * KC * OUT_DIM;
        #pragma unroll
        for (int it = 0; it < 2; it++) {              // B: 1024 cp16 (32 rows x 32)
            int idx = tid + THREADS * it;
            int k = idx >> 5, c = idx & 31;
            cp16(smb + B_OFF(st) + (k * B_STRIDE + c * 8) * 2, Wb + k * OUT_DIM + c * 8);
        }
        asm volatile("cp.async.commit_group;");
    };

    float acc[2][8][4];
    #pragma unroll
    for (int mt = 0; mt < 2; mt++)
        #pragma unroll
        for (int nt = 0; nt < 8; nt++)
            #pragma unroll
            for (int q = 0; q < 4; q++) acc[mt][nt][q] = 0.f;

    // ldmatrix lane-address components (bf16 units)
    const int a_row = (lane & 7) + ((lane >> 3) & 1) * 8;
    const int a_ks  = (lane >> 4) * 8;
    const int b_krw = (lane & 7) + ((lane >> 3) & 1) * 8;
    const int b_ns  = (lane >> 4) * 8;

    issue(0);
    issue(1);

    #pragma unroll 1
    for (int i = 0; i < NCH; i++) {
        if (i == NCH - 1) asm volatile("cp.async.wait_group 0;");
        else              asm volatile("cp.async.wait_group 1;");
        __syncthreads();

        const int st = i % NSTAGE;
        const uint32_t Ab = smb + A_OFF(st);
        const uint32_t Bb = smb + B_OFF(st);

        #pragma unroll
        for (int ks = 0; ks < 2; ks++) {
            const int k0 = ks * 16;
            uint32_t a[2][4];
            #pragma unroll
            for (int mt = 0; mt < 2; mt++)
                ldsm4(a[mt], Ab + ((wm * 32 + mt * 16 + a_row) * A_STRIDE + k0 + a_ks) * 2);
            uint32_t bf[4][4];
            #pragma unroll
            for (int ntt = 0; ntt < 4; ntt++)
                ldsm4t(bf[ntt], Bb + ((k0 + b_krw) * B_STRIDE + wn * 64 + ntt * 16 + b_ns) * 2);
            #pragma unroll
            for (int mt = 0; mt < 2; mt++)
                #pragma unroll
                for (int nt = 0; nt < 8; nt++)
                    mma_bf16(acc[mt][nt], a[mt], &bf[nt >> 1][(nt & 1) * 2]);
        }

        if (i + 2 < NCH) issue(i + 2);
    }
    __syncthreads();   // all reads of staging done before raw aliases it

    // -------- fragments -> raw smem with bias + relu --------
    {
        float* raw = sm;
        const float* bs = sm + SM_BIAS;
        #pragma unroll
        for (int mt = 0; mt < 2; mt++) {
            #pragma unroll
            for (int nt = 0; nt < 8; nt++) {
                int r0 = wm * 32 + mt * 16 + qr;
                int c0 = wn * 64 + nt * 8 + 2 * qc;
                raw[r0 * R_STRIDE + c0]           = fmaxf(acc[mt][nt][0] + bs[c0],     0.f);
                raw[r0 * R_STRIDE + c0 + 1]       = fmaxf(acc[mt][nt][1] + bs[c0 + 1], 0.f);
                raw[(r0 + 8) * R_STRIDE + c0]     = fmaxf(acc[mt][nt][2] + bs[c0],     0.f);
                raw[(r0 + 8) * R_STRIDE + c0 + 1] = fmaxf(acc[mt][nt][3] + bs[c0 + 1], 0.f);
            }
        }
    }
    __syncthreads();

    // -------- pass 1: gated residual + LN stats (thread per edge row) --------
    if (tid < TILE_M) {
        int r = tid;
        float* row = sm + r * R_STRIDE;
        const float4* ear = (const float4*)(ea + (size_t)min(e0 + r, E - 1) * NODE_DIM);
        float s = 0.f, ss = 0.f;
        #pragma unroll
        for (int j4 = 0; j4 < 32; j4++) {
            float4 eav = ear[j4];
            float ev[4] = {eav.x, eav.y, eav.z, eav.w};
            #pragma unroll
            for (int q = 0; q < 4; q++) {
                int j = j4 * 4 + q;
                float d = row[j];
                float g = row[128 + j];
                float sg = 1.0f / (1.0f + __expf(-g));
                float o = ev[q] + sg * d;
                row[j] = o;
                s += o; ss += o * o;
            }
        }
        float mu  = s * (1.0f / 128.0f);
        float inv = rsqrtf(ss * (1.0f / 128.0f) - mu * mu + EPS);
        sm[SM_MU + r]  = mu;
        sm[SM_INV + r] = inv;
    }
    __syncthreads();

    // -------- pass 2: normalize + coalesced float4 writes --------
    {
        float4 g4 = ((const float4*)eg)[lane];
        float4 b4 = ((const float4*)eb)[lane];
        #pragma unroll
        for (int rr = 0; rr < 8; rr++) {
            int r = wid * 8 + rr;
            if (r < ne) {
                const float* row = sm + r * R_STRIDE + lane * 4;
                float m  = sm[SM_MU + r];
                float iv = sm[SM_INV + r];
                float4 o;
                o.x = (row[0] - m) * iv * g4.x + b4.x;
                o.y = (row[1] - m) * iv * g4.y + b4.y;
                o.z = (row[2] - m) * iv * g4.z + b4.z;
                o.w = (row[3] - m) * iv * g4.w + b4.w;
                ((float4*)(out + (size_t)(e0 + r) * 128))[lane] = o;
            }
        }
    }
}

// ---------------------------------------------------------------------------
extern "C" void kernel_launch(void* const* d_in, const int* in_sizes, int n_in,
                              void* d_out, int out_size) {
    const float* x  = (const float*)d_in[0];
    const int*   ei = (const int*)  d_in[1];
    const float* ea = (const float*)d_in[2];
    const float* W  = (const float*)d_in[3];
    const float* b  = (const float*)d_in[4];
    const float* ng = (const float*)d_in[5];
    const float* nb = (const float*)d_in[6];
    const float* eg = (const float*)d_in[7];
    const float* eb = (const float*)d_in[8];
    float* out = (float*)d_out;

    int E = in_sizes[2] / NODE_DIM;   // 500000

    int ea_blocks = (E * (NODE_DIM / 4) + 255) / 256;
    prep_kernel<<<LN_BLOCKS + W_BLOCKS + ea_blocks, 256>>>(x, ng, nb, W, ea, E);

    cudaFuncSetAttribute(edge_kernel, cudaFuncAttributeMaxDynamicSharedMemorySize, SMEM_BYTES);
    edge_kernel<<<(E + TILE_M - 1) / TILE_M, THREADS, SMEM_BYTES>>>(ei, ea, b, eg, eb, out, E);
}